// round 17
// baseline (speedup 1.0000x reference)
#include <cuda_runtime.h>
#include <cuda_bf16.h>
#include <math.h>
#include <stdint.h>

// ---------------- problem constants ----------------
#define D_   1024
#define H_   8
#define E_   128
#define B_   4
#define S_   2048
#define NT_  (B_ * S_)
#define EPS_ 1e-6f

// ---------------- device scratch ----------------
__device__ float g_mod [NT_ * D_];
__device__ float g_h   [NT_ * D_];   // bf16 (half used)
__device__ float g_q   [NT_ * D_];   // bf16
__device__ float g_k   [NT_ * D_];
__device__ float g_v   [NT_ * D_];
__device__ float g_mod2[NT_ * D_];
__device__ float g_h2  [NT_ * D_];
__device__ float g_xt  [NT_ * D_];
__device__ float g_wint[D_ * D_];
__device__ float g_wft [D_ * D_];
__device__ float g_wqt [H_ * E_ * E_];  // bf16 pair-interleaved (half used)
__device__ float g_wkt [H_ * E_ * E_];
__device__ float g_wvt [H_ * E_ * E_];

__device__ __forceinline__ float elu1(float x) { return x > 0.f ? x : expm1f(x); }

__device__ __forceinline__ float f2tf(float f) {
  uint32_t u;
  asm("cvt.rna.tf32.f32 %0, %1;" : "=r"(u) : "f"(f));
  return __uint_as_float(u);
}
__device__ __forceinline__ float4 tf32x4(float4 v) {
  return make_float4(f2tf(v.x), f2tf(v.y), f2tf(v.z), f2tf(v.w));
}
__device__ __forceinline__ uint32_t packbf(float lo, float hi) {
  __nv_bfloat162 p = __floats2bfloat162_rn(lo, hi);
  return *(uint32_t*)&p;
}

__device__ __forceinline__ void mma_tf32(float* d, const uint32_t* a, const uint32_t* b) {
  asm volatile(
      "mma.sync.aligned.m16n8k8.row.col.f32.tf32.tf32.f32 "
      "{%0,%1,%2,%3}, {%4,%5,%6,%7}, {%8,%9}, {%0,%1,%2,%3};"
      : "+f"(d[0]), "+f"(d[1]), "+f"(d[2]), "+f"(d[3])
      : "r"(a[0]), "r"(a[1]), "r"(a[2]), "r"(a[3]), "r"(b[0]), "r"(b[1]));
}
__device__ __forceinline__ void mma_bf16(float* d, const uint32_t* a, const uint32_t* b) {
  asm volatile(
      "mma.sync.aligned.m16n8k16.row.col.f32.bf16.bf16.f32 "
      "{%0,%1,%2,%3}, {%4,%5,%6,%7}, {%8,%9}, {%0,%1,%2,%3};"
      : "+f"(d[0]), "+f"(d[1]), "+f"(d[2]), "+f"(d[3])
      : "r"(a[0]), "r"(a[1]), "r"(a[2]), "r"(a[3]), "r"(b[0]), "r"(b[1]));
}
__device__ __forceinline__ void ldsm4(uint32_t* r, uint32_t a) {
  asm volatile("ldmatrix.sync.aligned.m8n8.x4.shared.b16 {%0,%1,%2,%3}, [%4];"
               : "=r"(r[0]), "=r"(r[1]), "=r"(r[2]), "=r"(r[3]) : "r"(a));
}
__device__ __forceinline__ void ldsm4t(uint32_t* r, uint32_t a) {
  asm volatile("ldmatrix.sync.aligned.m8n8.x4.trans.shared.b16 {%0,%1,%2,%3}, [%4];"
               : "=r"(r[0]), "=r"(r[1]), "=r"(r[2]), "=r"(r[3]) : "r"(a));
}

__device__ __forceinline__ void cp16(float* s, const float* g) {
  uint32_t sa = (uint32_t)__cvta_generic_to_shared(s);
  asm volatile("cp.async.cg.shared.global [%0], [%1], 16;" :: "r"(sa), "l"(g));
}
#define CP_COMMIT() asm volatile("cp.async.commit_group;")
#define CP_WAIT0()  asm volatile("cp.async.wait_group 0;")
#define CP_WAIT1()  asm volatile("cp.async.wait_group 1;")

// ============================================================
// prep kernels
// ============================================================
__global__ void k_cvt(const float* __restrict__ in, float* __restrict__ out, int n4) {
  int i = blockIdx.x * blockDim.x + threadIdx.x;
  if (i < n4) ((float4*)out)[i] = tf32x4(((const float4*)in)[i]);
}

// head weights -> bf16 pair-interleaved (for QKV GEMM B-operand)
__global__ void k_cvtw3(const float* __restrict__ a, const float* __restrict__ b,
                        const float* __restrict__ c, uint32_t* __restrict__ oa,
                        uint32_t* __restrict__ ob, uint32_t* __restrict__ oc) {
  int i = blockIdx.x * blockDim.x + threadIdx.x;
  const float* in = blockIdx.y == 0 ? a : (blockIdx.y == 1 ? b : c);
  uint32_t* out = blockIdx.y == 0 ? oa : (blockIdx.y == 1 ? ob : oc);
  int head = i >> 13;
  int loc = i & 8191;
  int pr = loc >> 7, n = loc & 127;
  const float* W = in + head * E_ * E_;
  out[i] = packbf(W[(2 * pr) * E_ + n], W[(2 * pr + 1) * E_ + n]);
}

// ============================================================
// TF32 GEMM, 3-stage cp.async pipeline (dense / FFN).
// ============================================================
#define GBM 128
#define GBN 128
#define GBK 32
#define LDA_S 36
#define LDB_S 136
#define ST_SZ (GBM * LDA_S + GBK * LDB_S)
#define GEMM_SMEM (3 * ST_SZ * 4)

template <int MODE>
__device__ __forceinline__ void gemm_core(
    const float* __restrict__ A, int lda,
    const float* __restrict__ Bm, int ldb,
    float* __restrict__ C, int ldc, int K,
    const float* __restrict__ bias, const float* __restrict__ resid) {
  extern __shared__ float smg[];

  const int t = threadIdx.x;
  const int lane = t & 31, wid = t >> 5;
  const int g = lane >> 2, tg = lane & 3;
  const int wr = wid >> 2, wc = wid & 3;

  const int a_r = t >> 3;
  const int a_c = (t & 7) * 4;
  const int b_r = t >> 5;
  const int b_c = (t & 31) * 4;

  float acc[4][4][4];
#pragma unroll
  for (int i = 0; i < 4; i++)
#pragma unroll
    for (int j = 0; j < 4; j++)
#pragma unroll
      for (int r = 0; r < 4; r++) acc[i][j][r] = 0.f;

  auto load_stage = [&](int st, int k0) {
    float* as = smg + st * ST_SZ;
    float* bs = as + GBM * LDA_S;
#pragma unroll
    for (int i = 0; i < 4; i++) {
      int r = a_r + i * 32;
      cp16(&as[r * LDA_S + a_c], A + (size_t)r * lda + k0 + a_c);
    }
#pragma unroll
    for (int i = 0; i < 4; i++) {
      int r = b_r + i * 8;
      cp16(&bs[r * LDB_S + b_c], Bm + (size_t)(k0 + r) * ldb + b_c);
    }
  };

  load_stage(0, 0);
  CP_COMMIT();
  load_stage(1, GBK);
  CP_COMMIT();

  int cur = 0;
  for (int k0 = 0; k0 < K; k0 += GBK) {
    CP_WAIT1();
    __syncthreads();
    if (k0 + 2 * GBK < K) {
      int nxt = cur + 2; if (nxt >= 3) nxt -= 3;
      load_stage(nxt, k0 + 2 * GBK);
      CP_COMMIT();
    }
    const uint32_t* as = (const uint32_t*)(smg + cur * ST_SZ);
    const uint32_t* bs = as + GBM * LDA_S;
#pragma unroll
    for (int kk = 0; kk < GBK; kk += 8) {
      uint32_t af[4][4], bf[4][2];
#pragma unroll
      for (int i = 0; i < 4; i++) {
        int r0 = wr * 64 + i * 16;
        af[i][0] = as[(r0 + g) * LDA_S + kk + tg];
        af[i][1] = as[(r0 + g + 8) * LDA_S + kk + tg];
        af[i][2] = as[(r0 + g) * LDA_S + kk + tg + 4];
        af[i][3] = as[(r0 + g + 8) * LDA_S + kk + tg + 4];
      }
#pragma unroll
      for (int j = 0; j < 4; j++) {
        int c0 = wc * 32 + j * 8;
        bf[j][0] = bs[(kk + tg) * LDB_S + c0 + g];
        bf[j][1] = bs[(kk + tg + 4) * LDB_S + c0 + g];
      }
#pragma unroll
      for (int i = 0; i < 4; i++)
#pragma unroll
        for (int j = 0; j < 4; j++) mma_tf32(acc[i][j], af[i], bf[j]);
    }
    if (++cur == 3) cur = 0;
  }

#pragma unroll
  for (int i = 0; i < 4; i++) {
    int rA = wr * 64 + i * 16 + g;
    int rB = rA + 8;
#pragma unroll
    for (int j = 0; j < 4; j++) {
      int c = wc * 32 + j * 8 + 2 * tg;
      float2 o0 = make_float2(acc[i][j][0], acc[i][j][1]);
      float2 o1 = make_float2(acc[i][j][2], acc[i][j][3]);
      if (MODE == 1) {
        float2 bv = *(const float2*)(bias + c);
        float2 r0 = *(const float2*)(resid + (size_t)rA * ldc + c);
        float2 r1 = *(const float2*)(resid + (size_t)rB * ldc + c);
        o0.x = r0.x + elu1(o0.x + bv.x);
        o0.y = r0.y + elu1(o0.y + bv.y);
        o1.x = r1.x + elu1(o1.x + bv.x);
        o1.y = r1.y + elu1(o1.y + bv.y);
      }
      *(float2*)(C + (size_t)rA * ldc + c) = o0;
      *(float2*)(C + (size_t)rB * ldc + c) = o1;
    }
  }
}

__global__ void __launch_bounds__(256) k_gemm_dense(const float* __restrict__ A,
                                                    const float* __restrict__ W,
                                                    float* __restrict__ C) {
  const size_t moff = (size_t)blockIdx.y * GBM * D_;
  gemm_core<0>(A + moff, D_, W + blockIdx.x * GBN, D_,
               C + moff + blockIdx.x * GBN, D_, D_, nullptr, nullptr);
}

__global__ void __launch_bounds__(256) k_gemm_ffn(const float* __restrict__ A,
                                                  const float* __restrict__ W,
                                                  const float* __restrict__ bias,
                                                  const float* __restrict__ resid,
                                                  float* __restrict__ C) {
  const size_t moff = (size_t)blockIdx.y * GBM * D_;
  const size_t off = moff + blockIdx.x * GBN;
  gemm_core<1>(A + moff, D_, W + blockIdx.x * GBN, D_, C + off, D_, D_,
               bias + blockIdx.x * GBN, resid + off);
}

// ============================================================
// bf16 QKV GEMM: 128x128, K=128 single stage, 8 warps (2x4).
// All outputs plain row-major bf16.
// ============================================================
#define LAW 68
#define LBW 136
#define QKV_SMEM ((128 * LAW + 64 * LBW) * 4)

__global__ void __launch_bounds__(256) k_gemm_qkv(const float* __restrict__ Hm,
                                                  const float* __restrict__ Wq,
                                                  const float* __restrict__ Wk,
                                                  const float* __restrict__ Wv,
                                                  __nv_bfloat16* __restrict__ Oq,
                                                  __nv_bfloat16* __restrict__ Ok,
                                                  __nv_bfloat16* __restrict__ Ov) {
  extern __shared__ float smq[];
  float* a_s = smq;
  float* b_s = smq + 128 * LAW;

  const int which = blockIdx.z;
  const int bh = blockIdx.y;
  const int b = bh >> 3, h = bh & 7;

  const int t = threadIdx.x;
  const int lane = t & 31, wid = t >> 5;
  const int g = lane >> 2, tg = lane & 3;
  const int wr = wid >> 2, wc = wid & 3;

  const float* Aw = Hm + ((size_t)b * S_ + (size_t)blockIdx.x * 128) * (D_ / 2) + h * 64;
  const float* Wsel = which == 0 ? Wq : (which == 1 ? Wk : Wv);
  const float* Bw = Wsel + (size_t)h * 8192;

  {
    const int ar = t >> 1;
    const int ac0 = (t & 1) * 4;
#pragma unroll
    for (int i = 0; i < 8; i++) {
      int c = ac0 + i * 8;
      cp16(&a_s[ar * LAW + c], Aw + (size_t)ar * (D_ / 2) + c);
    }
    const int br = t >> 2;
    const int bc0 = (t & 3) * 4;
#pragma unroll
    for (int i = 0; i < 8; i++) {
      int c = bc0 + i * 16;
      cp16(&b_s[br * LBW + c], Bw + (size_t)br * 128 + c);
    }
  }
  CP_COMMIT();
  CP_WAIT0();
  __syncthreads();

  float acc[4][4][4];
#pragma unroll
  for (int i = 0; i < 4; i++)
#pragma unroll
    for (int j = 0; j < 4; j++)
#pragma unroll
      for (int r = 0; r < 4; r++) acc[i][j][r] = 0.f;

  const uint32_t* asw = (const uint32_t*)a_s;
  const uint32_t* bsw = (const uint32_t*)b_s;
#pragma unroll
  for (int kk = 0; kk < 8; kk++) {
    uint32_t af[4][4], bf[4][2];
#pragma unroll
    for (int i = 0; i < 4; i++) {
      int r0 = wr * 64 + i * 16;
      af[i][0] = asw[(r0 + g) * LAW + kk * 8 + tg];
      af[i][1] = asw[(r0 + g + 8) * LAW + kk * 8 + tg];
      af[i][2] = asw[(r0 + g) * LAW + kk * 8 + 4 + tg];
      af[i][3] = asw[(r0 + g + 8) * LAW + kk * 8 + 4 + tg];
    }
#pragma unroll
    for (int j = 0; j < 4; j++) {
      int c0 = wc * 32 + j * 8;
      bf[j][0] = bsw[(kk * 8 + tg) * LBW + c0 + g];
      bf[j][1] = bsw[(kk * 8 + 4 + tg) * LBW + c0 + g];
    }
#pragma unroll
    for (int i = 0; i < 4; i++)
#pragma unroll
      for (int j = 0; j < 4; j++) mma_bf16(acc[i][j], af[i], bf[j]);
  }

  __nv_bfloat16* Out = which == 0 ? Oq : (which == 1 ? Ok : Ov);
  uint32_t* Cw = (uint32_t*)(Out + ((size_t)bh * S_ + (size_t)blockIdx.x * 128) * E_);
#pragma unroll
  for (int i = 0; i < 4; i++) {
    int rA = wr * 64 + i * 16 + g;
    int rB = rA + 8;
#pragma unroll
    for (int j = 0; j < 4; j++) {
      int c = wc * 32 + j * 8 + 2 * tg;
      Cw[(size_t)rA * 64 + (c >> 1)] = packbf(acc[i][j][0], acc[i][j][1]);
      Cw[(size_t)rB * 64 + (c >> 1)] = packbf(acc[i][j][2], acc[i][j][3]);
    }
  }
}

// ============================================================
// LayerNorm, warp-per-row. BF16OUT: packed bf16 (h), else tf32.
// ============================================================
template <bool BF16OUT>
__global__ void __launch_bounds__(256) k_ln(const float* __restrict__ in,
                                            float* __restrict__ out,
                                            const float* __restrict__ gamma,
                                            const float* __restrict__ beta) {
  const int lane = threadIdx.x & 31;
  const size_t row = (size_t)blockIdx.x * 8 + (threadIdx.x >> 5);
  const float4* ip = (const float4*)(in + row * D_);
  float4 v[8];
  float s = 0.f, s2 = 0.f;
#pragma unroll
  for (int i = 0; i < 8; i++) {
    v[i] = ip[lane + i * 32];
    s  += v[i].x + v[i].y + v[i].z + v[i].w;
    s2 += v[i].x * v[i].x + v[i].y * v[i].y + v[i].z * v[i].z + v[i].w * v[i].w;
  }
#pragma unroll
  for (int off = 16; off; off >>= 1) {
    s  += __shfl_xor_sync(0xffffffffu, s, off);
    s2 += __shfl_xor_sync(0xffffffffu, s2, off);
  }
  const float mean = s * (1.f / D_);
  const float var  = s2 * (1.f / D_) - mean * mean;
  const float inv  = rsqrtf(var + EPS_);
#pragma unroll
  for (int i = 0; i < 8; i++) {
    float4 gm = ((const float4*)gamma)[lane + i * 32];
    float4 bb = ((const float4*)beta)[lane + i * 32];
    float4 o;
    o.x = (v[i].x - mean) * inv * gm.x + bb.x;
    o.y = (v[i].y - mean) * inv * gm.y + bb.y;
    o.z = (v[i].z - mean) * inv * gm.z + bb.z;
    o.w = (v[i].w - mean) * inv * gm.w + bb.w;
    if (BF16OUT) {
      uint2 pw = make_uint2(packbf(o.x, o.y), packbf(o.z, o.w));
      ((uint2*)(out + row * (D_ / 2)))[lane + i * 32] = pw;
    } else {
      ((float4*)(out + row * D_))[lane + i * 32] = tf32x4(o);
    }
  }
}

// ============================================================
// Flash attention, bf16. QT=128, KT=64, 8 warps.
// K + V both row-major 64x68 words; phase A non-trans ldmatrix,
// phase B trans ldmatrix on V. P in registers.
// ============================================================
#define QT 128
#define KTT 64
#define NKT (S_ / KTT)
#define LKW 68
#define ATTN_SMEM ((4 * 64 * LKW) * 4)

__global__ void __launch_bounds__(256) k_attn(const __nv_bfloat16* __restrict__ Qg,
                                              const __nv_bfloat16* __restrict__ Kg,
                                              const __nv_bfloat16* __restrict__ Vg,
                                              const float* __restrict__ modin,
                                              float* __restrict__ modout) {
  extern __shared__ float sm[];
  float* k_s = sm;                       // [2][64][LKW] words
  float* v_s = sm + 2 * 64 * LKW;        // [2][64][LKW] words

  const int t = threadIdx.x;
  const int lane = t & 31, w = t >> 5;
  const int g = lane >> 2, tg = lane & 3;
  const int row0 = w * 16;

  const int q0 = blockIdx.x * QT;
  const int h = blockIdx.y, b = blockIdx.z;
  const size_t bh = (size_t)b * H_ + h;

  const float* Kp = (const float*)(Kg + bh * S_ * E_);
  const float* Vp = (const float*)(Vg + bh * S_ * E_);

  // ---- Q fragments straight from gmem ----
  uint32_t qf[8][4];
  {
    const uint32_t* qw = (const uint32_t*)(Qg + (bh * S_ + q0) * E_);
#pragma unroll
    for (int kk = 0; kk < 8; kk++) {
      qf[kk][0] = qw[(row0 + g) * 64 + kk * 8 + tg];
      qf[kk][1] = qw[(row0 + g + 8) * 64 + kk * 8 + tg];
      qf[kk][2] = qw[(row0 + g) * 64 + kk * 8 + 4 + tg];
      qf[kk][3] = qw[(row0 + g + 8) * 64 + kk * 8 + 4 + tg];
    }
  }

  // ---- ldmatrix base addresses ----
  uint32_t ka_base[4];   // phase A, non-trans on K
  uint32_t va_base;      // phase B, trans on V
  {
    const int sec = lane >> 3, l = lane & 7;
    uint32_t kaddr = (uint32_t)__cvta_generic_to_shared(k_s);
    const int roff = sec >> 1, woff = (sec & 1) * 4;
#pragma unroll
    for (int jp = 0; jp < 4; jp++) {
      int row = (2 * jp + roff) * 8 + l;
      ka_base[jp] = kaddr + 4 * (row * LKW + woff);
    }
    uint32_t vaddr = (uint32_t)__cvta_generic_to_shared(v_s);
    // tiles: sec0 (k0, j), sec1 (k0+8, j), sec2 (k0, j+1), sec3 (k0+8, j+1)
    va_base = vaddr + 4 * ((((sec & 1) * 8) + l) * LKW + (sec >> 1) * 4);
  }

  // ---- cp.async loaders (identical pattern for K and V) ----
  const int k_r = t >> 2, k_c = t & 3;

  auto load_kv = [&](int st, int kt) {
    float* ks = k_s + st * 64 * LKW;
    float* vs = v_s + st * 64 * LKW;
    const float* kb = Kp + (size_t)kt * KTT * 64;
    const float* vb = Vp + (size_t)kt * KTT * 64;
#pragma unroll
    for (int i = 0; i < 4; i++) {
      int c = (k_c + i * 4) * 4;
      cp16(&ks[k_r * LKW + c], kb + (size_t)k_r * 64 + c);
      cp16(&vs[k_r * LKW + c], vb + (size_t)k_r * 64 + c);
    }
  };

  load_kv(0, 0);
  CP_COMMIT();

  float o[16][4];
#pragma unroll
  for (int j = 0; j < 16; j++)
#pragma unroll
    for (int r = 0; r < 4; r++) o[j][r] = 0.f;

  float mA = -1e30f, mB = -1e30f, lA = 0.f, lB = 0.f;

  for (int kt = 0; kt < NKT; kt++) {
    const int cur = kt & 1;
    CP_WAIT0();
    __syncthreads();
    if (kt + 1 < NKT) {
      load_kv(cur ^ 1, kt + 1);
      CP_COMMIT();
    }
    const uint32_t stoff = (uint32_t)(cur * 64 * LKW * 4);

    // ---- phase A: scores (16 x 64) = Q K^T ----
    float sc[8][4];
#pragma unroll
    for (int j = 0; j < 8; j++)
#pragma unroll
      for (int r = 0; r < 4; r++) sc[j][r] = 0.f;

#pragma unroll
    for (int kk = 0; kk < 8; kk++) {
#pragma unroll
      for (int jp = 0; jp < 4; jp++) {
        uint32_t bfr[4];
        ldsm4(bfr, ka_base[jp] + stoff + kk * 32);
        mma_bf16(sc[2 * jp],     qf[kk], bfr);
        mma_bf16(sc[2 * jp + 1], qf[kk], bfr + 2);
      }
    }

    // ---- register softmax (fp32) ----
    {
      float mtA = -1e30f, mtB = -1e30f;
#pragma unroll
      for (int j = 0; j < 8; j++) {
        mtA = fmaxf(mtA, fmaxf(sc[j][0], sc[j][1]));
        mtB = fmaxf(mtB, fmaxf(sc[j][2], sc[j][3]));
      }
      mtA = fmaxf(mtA, __shfl_xor_sync(0xffffffffu, mtA, 1));
      mtA = fmaxf(mtA, __shfl_xor_sync(0xffffffffu, mtA, 2));
      mtB = fmaxf(mtB, __shfl_xor_sync(0xffffffffu, mtB, 1));
      mtB = fmaxf(mtB, __shfl_xor_sync(0xffffffffu, mtB, 2));
      float mnA = fmaxf(mA, mtA), mnB = fmaxf(mB, mtB);
      float aA = __expf(mA - mnA), aB = __expf(mB - mnB);
      mA = mnA; mB = mnB;
      float sA = 0.f, sB = 0.f;
#pragma unroll
      for (int j = 0; j < 8; j++) {
        sc[j][0] = __expf(sc[j][0] - mnA);
        sc[j][1] = __expf(sc[j][1] - mnA);
        sc[j][2] = __expf(sc[j][2] - mnB);
        sc[j][3] = __expf(sc[j][3] - mnB);
        sA += sc[j][0] + sc[j][1];
        sB += sc[j][2] + sc[j][3];
      }
      sA += __shfl_xor_sync(0xffffffffu, sA, 1);
      sA += __shfl_xor_sync(0xffffffffu, sA, 2);
      sB += __shfl_xor_sync(0xffffffffu, sB, 1);
      sB += __shfl_xor_sync(0xffffffffu, sB, 2);
      lA = lA * aA + sA;
      lB = lB * aB + sB;
#pragma unroll
      for (int j = 0; j < 16; j++) {
        o[j][0] *= aA; o[j][1] *= aA;
        o[j][2] *= aB; o[j][3] *= aB;
      }
    }

    // ---- phase B: O += P V, V fragments via ldmatrix.trans ----
#pragma unroll
    for (int kk = 0; kk < 4; kk++) {
      uint32_t af[4];
      af[0] = packbf(sc[2 * kk][0],     sc[2 * kk][1]);
      af[1] = packbf(sc[2 * kk][2],     sc[2 * kk][3]);
      af[2] = packbf(sc[2 * kk + 1][0], sc[2 * kk + 1][1]);
      af[3] = packbf(sc[2 * kk + 1][2], sc[2 * kk + 1][3]);
      const uint32_t vk = va_base + stoff + (uint32_t)(kk * 16 * LKW * 4);
#pragma unroll
      for (int jp = 0; jp < 8; jp++) {
        uint32_t bfr[4];
        ldsm4t(bfr, vk + jp * 32);
        mma_bf16(o[2 * jp],     af, bfr);
        mma_bf16(o[2 * jp + 1], af, bfr + 2);
      }
    }
  }

  // ---- epilogue: normalize + residual (fp32) ----
  {
    float invA = 1.f / lA, invB = 1.f / lB;
    const int rA = q0 + row0 + g, rB = rA + 8;
#pragma unroll
    for (int j = 0; j < 16; j++) {
      int c = j * 8 + 2 * tg;
      size_t baseA = ((size_t)b * S_ + rA) * D_ + (size_t)h * E_ + c;
      size_t baseB = ((size_t)b * S_ + rB) * D_ + (size_t)h * E_ + c;
      float2 mAv = *(const float2*)(modin + baseA);
      float2 mBv = *(const float2*)(modin + baseB);
      float2 oA = make_float2(mAv.x + o[j][0] * invA, mAv.y + o[j][1] * invA);
      float2 oB = make_float2(mBv.x + o[j][2] * invB, mBv.y + o[j][3] * invB);
      *(float2*)(modout + baseA) = oA;
      *(float2*)(modout + baseB) = oB;
    }
  }
}

// ============================================================
extern "C" void kernel_launch(void* const* d_in, const int* in_sizes, int n_in,
                              void* d_out, int out_size) {
  const float* x     = (const float*)d_in[0];
  const float* W_in  = (const float*)d_in[1];
  const float* gamma = (const float*)d_in[2];
  const float* beta  = (const float*)d_in[3];
  const float* Wq    = (const float*)d_in[4];
  const float* Wk    = (const float*)d_in[5];
  const float* Wv    = (const float*)d_in[6];
  const float* Wf    = (const float*)d_in[7];
  const float* bf    = (const float*)d_in[8];
  float* out = (float*)d_out;

  float *mod, *h, *q, *k, *v, *mod2, *h2;
  float *xt, *wint, *wft, *wqt, *wkt, *wvt;
  cudaGetSymbolAddress((void**)&mod,  g_mod);
  cudaGetSymbolAddress((void**)&h,    g_h);
  cudaGetSymbolAddress((void**)&q,    g_q);
  cudaGetSymbolAddress((void**)&k,    g_k);
  cudaGetSymbolAddress((void**)&v,    g_v);
  cudaGetSymbolAddress((void**)&mod2, g_mod2);
  cudaGetSymbolAddress((void**)&h2,   g_h2);
  cudaGetSymbolAddress((void**)&xt,   g_xt);
  cudaGetSymbolAddress((void**)&wint, g_wint);
  cudaGetSymbolAddress((void**)&wft,  g_wft);
  cudaGetSymbolAddress((void**)&wqt,  g_wqt);
  cudaGetSymbolAddress((void**)&wkt,  g_wkt);
  cudaGetSymbolAddress((void**)&wvt,  g_wvt);

  __nv_bfloat16* qb = (__nv_bfloat16*)q;
  __nv_bfloat16* kb = (__nv_bfloat16*)k;
  __nv_bfloat16* vb = (__nv_bfloat16*)v;

  cudaFuncSetAttribute(k_gemm_dense, cudaFuncAttributeMaxDynamicSharedMemorySize, GEMM_SMEM);
  cudaFuncSetAttribute(k_gemm_ffn,   cudaFuncAttributeMaxDynamicSharedMemorySize, GEMM_SMEM);
  cudaFuncSetAttribute(k_gemm_qkv,   cudaFuncAttributeMaxDynamicSharedMemorySize, QKV_SMEM);
  cudaFuncSetAttribute(k_attn,       cudaFuncAttributeMaxDynamicSharedMemorySize, ATTN_SMEM);

  // ---- prep conversions ----
  k_cvt<<<(NT_ * D_ / 4 + 255) / 256, 256>>>(x, xt, NT_ * D_ / 4);
  k_cvt<<<(D_ * D_ / 4 + 255) / 256, 256>>>(W_in, wint, D_ * D_ / 4);
  k_cvt<<<(D_ * D_ / 4 + 255) / 256, 256>>>(Wf, wft, D_ * D_ / 4);
  dim3 gw((H_ * E_ * E_ / 2 + 255) / 256, 3);
  k_cvtw3<<<gw, 256>>>(Wq, Wk, Wv, (uint32_t*)wqt, (uint32_t*)wkt, (uint32_t*)wvt);

  dim3 gdense(D_ / GBN, NT_ / GBM);     // (8, 64)
  k_gemm_dense<<<gdense, 256, GEMM_SMEM>>>(xt, wint, mod);

  k_ln<true><<<NT_ / 8, 256>>>(mod, h, gamma, beta);   // h as bf16

  dim3 gqkv(S_ / GBM, B_ * H_, 3);      // (16, 32, 3)
  k_gemm_qkv<<<gqkv, 256, QKV_SMEM>>>(h, wqt, wkt, wvt, qb, kb, vb);

  dim3 gattn(S_ / QT, H_, B_);          // (16, 8, 4)
  k_attn<<<gattn, 256, ATTN_SMEM>>>(qb, kb, vb, mod, mod2);

  k_ln<false><<<NT_ / 8, 256>>>(mod2, h2, gamma, beta);

  k_gemm_ffn<<<gdense, 256, GEMM_SMEM>>>(h2, wft, bf, mod2, out);
}